// round 1
// baseline (speedup 1.0000x reference)
#include <cuda_runtime.h>

// CRF token-classifier NLL, fused.
// B=64, S=512, H=768, L=3. Output: scalar fp32 loss.
//
// Kernel 1: per (batch, 64-step chunk): emissions (hidden@W+b) + log-semiring
//           3x3 transition-matrix tree reduction + gold-score partial.
// Kernel 2: per batch: combine 8 chunk matrices, start/end/gold, loss mean.

#define Bn 64
#define Sn 512
#define Hn 768
#define CHUNK 64
#define NCH (Sn / CHUNK) // 8
#define T1 256

// scratch (no allocations allowed)
__device__ float g_M[Bn][NCH][9];
__device__ float g_gold[Bn][NCH];
__device__ float g_alpha0[Bn][3];

__device__ __forceinline__ float lse3(float a, float b, float c) {
    float m = fmaxf(a, fmaxf(b, c));
    return m + __logf(__expf(a - m) + __expf(b - m) + __expf(c - m));
}

__global__ __launch_bounds__(T1) void crf_k1(
    const float* __restrict__ hidden, const float* __restrict__ W,
    const float* __restrict__ bias, const float* __restrict__ start,
    const float* __restrict__ trans, const int* __restrict__ mask,
    const int* __restrict__ labels)
{
    const int chunk = blockIdx.x;
    const int batch = blockIdx.y;
    const int tid = threadIdx.x, lane = tid & 31, wid = tid >> 5;

    __shared__ float w0[Hn], w1[Hn], w2[Hn];   // W transposed (conflict-free)
    __shared__ float em[CHUNK][4];             // emissions for this chunk
    __shared__ float mats[CHUNK][9];           // log-semiring matrices
    __shared__ float tmp[CHUNK / 2][9];
    __shared__ float sgold[2];
    __shared__ float str[9];                   // transitions

    // stage W (transposed) and transitions
    for (int i = tid; i < Hn; i += T1) {
        w0[i] = W[i * 3 + 0];
        w1[i] = W[i * 3 + 1];
        w2[i] = W[i * 3 + 2];
    }
    if (tid < 9) str[tid] = trans[tid];
    __syncthreads();

    const float* hb = hidden + ((size_t)batch * Sn + (size_t)chunk * CHUNK) * Hn;
    float bb[3] = {bias[0], bias[1], bias[2]};

    // ---- emissions: each warp handles groups of 4 timesteps; lane covers
    //      h = 4*lane + 128*k (full 768 per warp). float4 loads, W float4 LDS
    //      amortized over 4 timesteps.
    for (int g = wid; g < CHUNK / 4; g += 8) {
        const int s0 = g * 4;
        float acc[4][3];
        #pragma unroll
        for (int t = 0; t < 4; t++)
            #pragma unroll
            for (int j = 0; j < 3; j++) acc[t][j] = 0.0f;

        #pragma unroll
        for (int k = 0; k < 6; k++) {
            const int h = 4 * lane + 128 * k;
            float4 v0 = *(const float4*)(w0 + h);
            float4 v1 = *(const float4*)(w1 + h);
            float4 v2 = *(const float4*)(w2 + h);
            #pragma unroll
            for (int t = 0; t < 4; t++) {
                float4 x = *(const float4*)(hb + (size_t)(s0 + t) * Hn + h);
                acc[t][0] += x.x * v0.x + x.y * v0.y + x.z * v0.z + x.w * v0.w;
                acc[t][1] += x.x * v1.x + x.y * v1.y + x.z * v1.z + x.w * v1.w;
                acc[t][2] += x.x * v2.x + x.y * v2.y + x.z * v2.z + x.w * v2.w;
            }
        }
        #pragma unroll
        for (int off = 16; off; off >>= 1)
            #pragma unroll
            for (int t = 0; t < 4; t++)
                #pragma unroll
                for (int j = 0; j < 3; j++)
                    acc[t][j] += __shfl_xor_sync(0xffffffffu, acc[t][j], off);
        if (lane == 0) {
            #pragma unroll
            for (int t = 0; t < 4; t++)
                #pragma unroll
                for (int j = 0; j < 3; j++)
                    em[s0 + t][j] = acc[t][j] + bb[j];
        }
    }
    __syncthreads();

    // ---- build per-step matrices + gold partials (one thread per timestep)
    float gp = 0.0f;
    if (tid < CHUNK) {
        const int s = chunk * CHUNK + tid;
        const int mval = (s >= 1) ? mask[batch * Sn + s] : 0;
        const bool act = (s >= 1) && (mval > 0);
        float row[9];
        if (act) {
            #pragma unroll
            for (int i = 0; i < 3; i++)
                #pragma unroll
                for (int j = 0; j < 3; j++)
                    row[i * 3 + j] = str[i * 3 + j] + em[tid][j];
        } else {
            #pragma unroll
            for (int e = 0; e < 9; e++)
                row[e] = (e == 0 || e == 4 || e == 8) ? 0.0f : -1e30f;
        }
        #pragma unroll
        for (int e = 0; e < 9; e++) mats[tid][e] = row[e];

        if (s >= 1) {
            int lg = labels[batch * Sn + s];     int tg = lg < 0 ? 0 : lg;
            int lp = labels[batch * Sn + s - 1]; int tp = lp < 0 ? 0 : lp;
            float m = (mval > 0) ? 1.0f : 0.0f;
            gp = (em[tid][tg] + str[tp * 3 + tg]) * m;
        }
    }
    if (chunk == 0 && tid < 3)
        g_alpha0[batch][tid] = start[tid] + em[0][tid];

    // gold partial reduce over warps 0,1 (exactly tid<64)
    if (wid < 2) {
        #pragma unroll
        for (int off = 16; off; off >>= 1)
            gp += __shfl_xor_sync(0xffffffffu, gp, off);
        if (lane == 0) sgold[wid] = gp;
    }

    // ---- ordered tree reduction of log-semiring matrices
    for (int n = CHUNK; n > 1; n >>= 1) {
        __syncthreads();
        const int half = n >> 1;
        for (int idx = tid; idx < half * 9; idx += T1) {
            const int p = idx / 9, e = idx - p * 9;
            const int i = e / 3, kk = e - i * 3;
            float x0 = mats[2 * p][i * 3 + 0] + mats[2 * p + 1][0 + kk];
            float x1 = mats[2 * p][i * 3 + 1] + mats[2 * p + 1][3 + kk];
            float x2 = mats[2 * p][i * 3 + 2] + mats[2 * p + 1][6 + kk];
            tmp[p][e] = lse3(x0, x1, x2);
        }
        __syncthreads();
        for (int idx = tid; idx < half * 9; idx += T1) {
            const int p = idx / 9, e = idx - p * 9;
            mats[p][e] = tmp[p][e];
        }
    }
    __syncthreads();
    if (tid < 9) g_M[batch][chunk][tid] = mats[0][tid];
    if (tid == 0) g_gold[batch][chunk] = sgold[0] + sgold[1];
}

__global__ __launch_bounds__(64) void crf_k2(
    const int* __restrict__ mask, const int* __restrict__ labels,
    const float* __restrict__ endt, float* __restrict__ out)
{
    const int b = threadIdx.x; // 64 threads, one batch each
    float val;
    {
        // last index with mask>0 (handles any pattern; mask[:,0]=1 per ref)
        const int4* mr = (const int4*)(mask + (size_t)b * Sn);
        int last = 0;
        #pragma unroll 4
        for (int i = 0; i < Sn / 4; i++) {
            int4 v = mr[i];
            if (v.x > 0) last = 4 * i + 0;
            if (v.y > 0) last = 4 * i + 1;
            if (v.z > 0) last = 4 * i + 2;
            if (v.w > 0) last = 4 * i + 3;
        }

        // combine chunk matrices left-to-right
        float M[9];
        #pragma unroll
        for (int e = 0; e < 9; e++) M[e] = g_M[b][0][e];
        for (int c = 1; c < NCH; c++) {
            float Nm[9], R[9];
            #pragma unroll
            for (int e = 0; e < 9; e++) Nm[e] = g_M[b][c][e];
            #pragma unroll
            for (int i = 0; i < 3; i++)
                #pragma unroll
                for (int k = 0; k < 3; k++)
                    R[i * 3 + k] = lse3(M[i * 3 + 0] + Nm[0 + k],
                                        M[i * 3 + 1] + Nm[3 + k],
                                        M[i * 3 + 2] + Nm[6 + k]);
            #pragma unroll
            for (int e = 0; e < 9; e++) M[e] = R[e];
        }

        float al0 = g_alpha0[b][0], al1 = g_alpha0[b][1], al2 = g_alpha0[b][2];
        float af0 = lse3(al0 + M[0], al1 + M[3], al2 + M[6]);
        float af1 = lse3(al0 + M[1], al1 + M[4], al2 + M[7]);
        float af2 = lse3(al0 + M[2], al1 + M[5], al2 + M[8]);
        float logz = lse3(af0 + endt[0], af1 + endt[1], af2 + endt[2]);

        int l0 = labels[(size_t)b * Sn];        int t0 = l0 < 0 ? 0 : l0;
        int ll = labels[(size_t)b * Sn + last]; int lt = ll < 0 ? 0 : ll;
        float score = g_alpha0[b][t0] + endt[lt];
        #pragma unroll
        for (int c = 0; c < NCH; c++) score += g_gold[b][c];
        val = score - logz;
    }

    // mean over 64 -> negate
    #pragma unroll
    for (int off = 16; off; off >>= 1)
        val += __shfl_xor_sync(0xffffffffu, val, off);
    __shared__ float sh[2];
    if ((b & 31) == 0) sh[b >> 5] = val;
    __syncthreads();
    if (b == 0) out[0] = -(sh[0] + sh[1]) * (1.0f / 64.0f);
}

extern "C" void kernel_launch(void* const* d_in, const int* in_sizes, int n_in,
                              void* d_out, int out_size) {
    const float* hidden = (const float*)d_in[0];
    const float* W      = (const float*)d_in[1];
    const float* bias   = (const float*)d_in[2];
    const float* start  = (const float*)d_in[3];
    const float* endt   = (const float*)d_in[4];
    const float* trans  = (const float*)d_in[5];
    const int*   mask   = (const int*)d_in[6];
    const int*   labels = (const int*)d_in[7];

    crf_k1<<<dim3(NCH, Bn), T1>>>(hidden, W, bias, start, trans, mask, labels);
    crf_k2<<<1, 64>>>(mask, labels, endt, (float*)d_out);
}

// round 2
// speedup vs baseline: 1.3539x; 1.3539x over previous
#include <cuda_runtime.h>

// CRF token-classifier NLL, fused. B=64, S=512, H=768, L=3. Output: scalar.
//
// Kernel 1: per (batch, 64-step chunk): emissions (hidden@W+b), log-semiring
//           3x3 matrix tree reduction, gold-score partial, local last-mask idx.
// Kernel 2: per batch (1 thread): combine 8 chunk matrices + start/end/gold,
//           mean-reduce. All heavy/parallel work lives in k1.

#define Bn 64
#define Sn 512
#define Hn 768
#define CHUNK 64
#define NCH (Sn / CHUNK) // 8
#define T1 256

// scratch (no allocations allowed)
__device__ float g_M[Bn][NCH][9];
__device__ float g_gold[Bn][NCH];
__device__ float g_alpha0[Bn][3];
__device__ int   g_last[Bn][NCH];

__device__ __forceinline__ float lse3(float a, float b, float c) {
    float m = fmaxf(a, fmaxf(b, c));
    return m + __logf(__expf(a - m) + __expf(b - m) + __expf(c - m));
}

__global__ __launch_bounds__(T1) void crf_k1(
    const float* __restrict__ hidden, const float* __restrict__ W,
    const float* __restrict__ bias, const float* __restrict__ start,
    const float* __restrict__ trans, const int* __restrict__ mask,
    const int* __restrict__ labels)
{
    const int chunk = blockIdx.x;
    const int batch = blockIdx.y;
    const int tid = threadIdx.x, lane = tid & 31, wid = tid >> 5;

    __shared__ float w0[Hn], w1[Hn], w2[Hn];   // W transposed (conflict-free)
    __shared__ float em[CHUNK][4];             // emissions for this chunk
    __shared__ float mats[CHUNK][9];           // log-semiring matrices
    __shared__ float tmp[CHUNK / 2][9];
    __shared__ float sgold[2];
    __shared__ int   slast[2];
    __shared__ float str[9];                   // transitions

    // stage W (transposed) and transitions
    for (int i = tid; i < Hn; i += T1) {
        w0[i] = W[i * 3 + 0];
        w1[i] = W[i * 3 + 1];
        w2[i] = W[i * 3 + 2];
    }
    if (tid < 9) str[tid] = trans[tid];
    __syncthreads();

    const float* hb = hidden + ((size_t)batch * Sn + (size_t)chunk * CHUNK) * Hn;
    float bb[3] = {bias[0], bias[1], bias[2]};

    // ---- emissions: each warp handles groups of 4 timesteps; lane covers
    //      h = 4*lane + 128*k. float4 GMEM loads, W float4 LDS amortized x4.
    for (int g = wid; g < CHUNK / 4; g += 8) {
        const int s0 = g * 4;
        float acc[4][3];
        #pragma unroll
        for (int t = 0; t < 4; t++)
            #pragma unroll
            for (int j = 0; j < 3; j++) acc[t][j] = 0.0f;

        #pragma unroll
        for (int k = 0; k < 6; k++) {
            const int h = 4 * lane + 128 * k;
            float4 v0 = *(const float4*)(w0 + h);
            float4 v1 = *(const float4*)(w1 + h);
            float4 v2 = *(const float4*)(w2 + h);
            #pragma unroll
            for (int t = 0; t < 4; t++) {
                float4 x = *(const float4*)(hb + (size_t)(s0 + t) * Hn + h);
                acc[t][0] += x.x * v0.x + x.y * v0.y + x.z * v0.z + x.w * v0.w;
                acc[t][1] += x.x * v1.x + x.y * v1.y + x.z * v1.z + x.w * v1.w;
                acc[t][2] += x.x * v2.x + x.y * v2.y + x.z * v2.z + x.w * v2.w;
            }
        }
        #pragma unroll
        for (int off = 16; off; off >>= 1)
            #pragma unroll
            for (int t = 0; t < 4; t++)
                #pragma unroll
                for (int j = 0; j < 3; j++)
                    acc[t][j] += __shfl_xor_sync(0xffffffffu, acc[t][j], off);
        if (lane == 0) {
            #pragma unroll
            for (int t = 0; t < 4; t++)
                #pragma unroll
                for (int j = 0; j < 3; j++)
                    em[s0 + t][j] = acc[t][j] + bb[j];
        }
    }
    __syncthreads();

    // ---- per-step matrices + gold partials + local last-mask index
    float gp = 0.0f;
    int   lc = -1;   // local candidate for last masked position
    if (tid < CHUNK) {
        const int s = chunk * CHUNK + tid;
        const int mval = mask[batch * Sn + s];
        lc = (mval > 0) ? s : -1;
        const bool act = (s >= 1) && (mval > 0);
        float row[9];
        if (act) {
            #pragma unroll
            for (int i = 0; i < 3; i++)
                #pragma unroll
                for (int j = 0; j < 3; j++)
                    row[i * 3 + j] = str[i * 3 + j] + em[tid][j];
        } else {
            #pragma unroll
            for (int e = 0; e < 9; e++)
                row[e] = (e == 0 || e == 4 || e == 8) ? 0.0f : -1e30f;
        }
        #pragma unroll
        for (int e = 0; e < 9; e++) mats[tid][e] = row[e];

        if (s >= 1) {
            int lg = labels[batch * Sn + s];     int tg = lg < 0 ? 0 : lg;
            int lp = labels[batch * Sn + s - 1]; int tp = lp < 0 ? 0 : lp;
            float m = (mval > 0) ? 1.0f : 0.0f;
            gp = (em[tid][tg] + str[tp * 3 + tg]) * m;
        }
    }
    if (chunk == 0 && tid < 3)
        g_alpha0[batch][tid] = start[tid] + em[0][tid];

    // reductions over warps 0,1 (exactly tid<64): gold sum + last-idx max
    if (wid < 2) {
        #pragma unroll
        for (int off = 16; off; off >>= 1) {
            gp += __shfl_xor_sync(0xffffffffu, gp, off);
            lc  = max(lc, __shfl_xor_sync(0xffffffffu, lc, off));
        }
        if (lane == 0) { sgold[wid] = gp; slast[wid] = lc; }
    }

    // ---- ordered tree reduction of log-semiring matrices
    for (int n = CHUNK; n > 1; n >>= 1) {
        __syncthreads();
        const int half = n >> 1;
        for (int idx = tid; idx < half * 9; idx += T1) {
            const int p = idx / 9, e = idx - p * 9;
            const int i = e / 3, kk = e - i * 3;
            float x0 = mats[2 * p][i * 3 + 0] + mats[2 * p + 1][0 + kk];
            float x1 = mats[2 * p][i * 3 + 1] + mats[2 * p + 1][3 + kk];
            float x2 = mats[2 * p][i * 3 + 2] + mats[2 * p + 1][6 + kk];
            tmp[p][e] = lse3(x0, x1, x2);
        }
        __syncthreads();
        for (int idx = tid; idx < half * 9; idx += T1) {
            const int p = idx / 9, e = idx - p * 9;
            mats[p][e] = tmp[p][e];
        }
    }
    __syncthreads();
    if (tid < 9) g_M[batch][chunk][tid] = mats[0][tid];
    if (tid == 0) {
        g_gold[batch][chunk] = sgold[0] + sgold[1];
        g_last[batch][chunk] = max(slast[0], slast[1]);
    }
}

__global__ __launch_bounds__(64) void crf_k2(
    const int* __restrict__ labels, const float* __restrict__ endt,
    float* __restrict__ out)
{
    const int b = threadIdx.x; // 64 threads, one batch each
    float val;
    {
        // last masked index from per-chunk partial maxima
        int last = 0;
        #pragma unroll
        for (int c = 0; c < NCH; c++) last = max(last, g_last[b][c]);

        // combine chunk matrices left-to-right
        float M[9];
        #pragma unroll
        for (int e = 0; e < 9; e++) M[e] = g_M[b][0][e];
        #pragma unroll
        for (int c = 1; c < NCH; c++) {
            float Nm[9], R[9];
            #pragma unroll
            for (int e = 0; e < 9; e++) Nm[e] = g_M[b][c][e];
            #pragma unroll
            for (int i = 0; i < 3; i++)
                #pragma unroll
                for (int k = 0; k < 3; k++)
                    R[i * 3 + k] = lse3(M[i * 3 + 0] + Nm[0 + k],
                                        M[i * 3 + 1] + Nm[3 + k],
                                        M[i * 3 + 2] + Nm[6 + k]);
            #pragma unroll
            for (int e = 0; e < 9; e++) M[e] = R[e];
        }

        float al0 = g_alpha0[b][0], al1 = g_alpha0[b][1], al2 = g_alpha0[b][2];
        float af0 = lse3(al0 + M[0], al1 + M[3], al2 + M[6]);
        float af1 = lse3(al0 + M[1], al1 + M[4], al2 + M[7]);
        float af2 = lse3(al0 + M[2], al1 + M[5], al2 + M[8]);
        float logz = lse3(af0 + endt[0], af1 + endt[1], af2 + endt[2]);

        int l0 = labels[(size_t)b * Sn];        int t0 = l0 < 0 ? 0 : l0;
        int ll = labels[(size_t)b * Sn + last]; int lt = ll < 0 ? 0 : ll;
        float score = g_alpha0[b][t0] + endt[lt];
        #pragma unroll
        for (int c = 0; c < NCH; c++) score += g_gold[b][c];
        val = score - logz;
    }

    // mean over 64 -> negate
    #pragma unroll
    for (int off = 16; off; off >>= 1)
        val += __shfl_xor_sync(0xffffffffu, val, off);
    __shared__ float sh[2];
    if ((b & 31) == 0) sh[b >> 5] = val;
    __syncthreads();
    if (b == 0) out[0] = -(sh[0] + sh[1]) * (1.0f / 64.0f);
}

extern "C" void kernel_launch(void* const* d_in, const int* in_sizes, int n_in,
                              void* d_out, int out_size) {
    const float* hidden = (const float*)d_in[0];
    const float* W      = (const float*)d_in[1];
    const float* bias   = (const float*)d_in[2];
    const float* start  = (const float*)d_in[3];
    const float* endt   = (const float*)d_in[4];
    const float* trans  = (const float*)d_in[5];
    const int*   mask   = (const int*)d_in[6];
    const int*   labels = (const int*)d_in[7];

    crf_k1<<<dim3(NCH, Bn), T1>>>(hidden, W, bias, start, trans, mask, labels);
    crf_k2<<<1, 64>>>(labels, endt, (float*)d_out);
}